// round 3
// baseline (speedup 1.0000x reference)
#include <cuda_runtime.h>
#include <cuda_fp16.h>
#include <cstdint>

#define PADN 4194304
#define OUTN 4000000
#define FULLMASK 0xffffffffu

// fp16 scratch: 8 batches x 2^22 halves = 64 MB
static __device__ __half g_work[(size_t)8 * PADN];
static __device__ float g_y[8 * 1024];

// ---------------------------------------------------------------------------
// Kernel 1: y[b] = WHT_1024(x[b] * B[0:1024]). 8 warps, warp per batch.
// (First full-size FWHT collapses: input support is [0,1024).)
// ---------------------------------------------------------------------------
__global__ void __launch_bounds__(256) k_y(const float* __restrict__ x,
                                           const float* __restrict__ B) {
  const int w = threadIdx.x >> 5;
  const int l = threadIdx.x & 31;
  float e[32];
#pragma unroll
  for (int j = 0; j < 32; j++) {
    int i = j * 32 + l;
    e[j] = x[w * 1024 + i] * B[i];
  }
  // lane-bit stages h=1..16 via shfl
#pragma unroll
  for (int h = 1; h <= 16; h <<= 1) {
    const float sg = (l & h) ? -1.0f : 1.0f;
#pragma unroll
    for (int j = 0; j < 32; j++) {
      float p = __shfl_xor_sync(FULLMASK, e[j], h);
      e[j] = fmaf(sg, e[j], p);
    }
  }
  // register-bit stages h=32..512
#pragma unroll
  for (int m = 1; m < 32; m <<= 1) {
#pragma unroll
    for (int j = 0; j < 32; j++) {
      if ((j & m) == 0) {
        float a = e[j], b = e[j | m];
        e[j] = a + b;
        e[j | m] = a - b;
      }
    }
  }
#pragma unroll
  for (int j = 0; j < 32; j++) g_y[w * 1024 + j * 32 + l] = e[j];
}

// ---------------------------------------------------------------------------
// Pass A (no shuffles): per 2048-chunk, gather t = y[Pi&1023]*G, then 2048-pt
// WHT via two register phases + one swizzled smem exchange. Warp w = batch w.
// Element index bits within chunk: [4:0]=k/lane, [10:5]=j.
//   phase 1: thread owns idx = j*32+l (j=0..63)  -> butterflies on bits 5..10
//   phase 2: thread owns idx = b*1024+l*32+k     -> butterflies on bits 0..4
// Exchange swizzle: addr = idx ^ ((idx>>5)&31)  (conflict-free both sides).
// ---------------------------------------------------------------------------
__global__ void __launch_bounds__(256, 3) k_passA(const float* __restrict__ G,
                                                  const int* __restrict__ Pi) {
  extern __shared__ float s_ex[];           // 8 warps * 2048 floats = 64 KB
  float* s_y = s_ex;                        // first 8192 floats alias: y table
  const int tid = threadIdx.x;
  const int w = tid >> 5, l = tid & 31;
  const size_t base = (size_t)blockIdx.x * 2048;

  // stage the 8x1024 y table
#pragma unroll
  for (int i = tid; i < 8192; i += 256) s_y[i] = g_y[i];
  __syncthreads();

  // gather + multiply by G, coalesced order idx = j*32+l
  const float* yb = s_y + w * 1024;
  float e[64];
#pragma unroll
  for (int j = 0; j < 64; j++) {
    size_t gi = base + j * 32 + l;
    e[j] = yb[Pi[gi] & 1023] * G[gi];
  }
  __syncthreads();  // protect s_y until every warp finished gathering

  // phase 1: butterflies over j-bits (element bits 5..10)
#pragma unroll
  for (int m = 1; m < 64; m <<= 1) {
#pragma unroll
    for (int j = 0; j < 64; j++) {
      if ((j & m) == 0) {
        float a = e[j], b = e[j | m];
        e[j] = a + b;
        e[j | m] = a - b;
      }
    }
  }

  // swizzled exchange (warp-private 2048-float region)
  float* ex = s_ex + w * 2048;
#pragma unroll
  for (int j = 0; j < 64; j++) {
    int idx = j * 32 + l;
    ex[idx ^ ((idx >> 5) & 31)] = e[j];
  }
  __syncwarp();
#pragma unroll
  for (int b = 0; b < 2; b++)
#pragma unroll
    for (int k = 0; k < 32; k++) {
      int idx = b * 1024 + l * 32 + k;
      e[b * 32 + k] = ex[idx ^ ((idx >> 5) & 31)];
    }

  // phase 2: butterflies over k-bits (element bits 0..4)
#pragma unroll
  for (int m = 1; m < 32; m <<= 1) {
#pragma unroll
    for (int b = 0; b < 2; b++)
#pragma unroll
      for (int k = 0; k < 32; k++) {
        if ((k & m) == 0) {
          float a = e[b * 32 + k], bb = e[b * 32 + (k | m)];
          e[b * 32 + k] = a + bb;
          e[b * 32 + (k | m)] = a - bb;
        }
      }
  }

  // fp16 store: thread owns two contiguous 32-element runs -> 4x uint4
  __half* o = g_work + (size_t)w * PADN + base;
#pragma unroll
  for (int b = 0; b < 2; b++) {
    __half h[32];
#pragma unroll
    for (int k = 0; k < 32; k++) h[k] = __float2half_rn(e[b * 32 + k]);
    const uint4* hv = (const uint4*)h;
    uint4* dst = (uint4*)(o + b * 1024 + l * 32);
    dst[0] = hv[0];
    dst[1] = hv[1];
    dst[2] = hv[2];
    dst[3] = hv[3];
  }
}

// ---------------------------------------------------------------------------
// Pass B: 2048-pt WHT across chunks (stride 2048). Tile = 2048 rows x 8 cols
// (64 KB fp32 smem), 256 threads, warp w owns column w. Two register phases
// joined by a warp-private swizzled exchange; output fused with *S and the
// 4,000,000 truncation. Swizzle: addr(c,r) = c*2048 + (r ^ ((r>>6)&31)).
// ---------------------------------------------------------------------------
__global__ void __launch_bounds__(256, 3) k_passB(const float* __restrict__ S,
                                                  float* __restrict__ out) {
  extern __shared__ float tile[];  // 8 * 2048 floats
  const int tid = threadIdx.x;
  const int b = blockIdx.y;
  const int c0 = blockIdx.x * 8;
  const __half* wrk = g_work + (size_t)b * PADN;

  // stage in: one uint4 (8 halfs = one row slice) per thread per iteration
#pragma unroll
  for (int i = 0; i < 8; i++) {
    int r = i * 256 + tid;
    uint4 v = *(const uint4*)(wrk + (size_t)r * 2048 + c0);
    const __half* hv = (const __half*)&v;
    int rs = r ^ ((r >> 6) & 31);
#pragma unroll
    for (int c = 0; c < 8; c++) tile[c * 2048 + rs] = __half2float(hv[c]);
  }
  __syncthreads();

  const int w = tid >> 5, l = tid & 31;
  float* col = tile + w * 2048;
  float e[64];

  // phase 1: lane owns rows [l*64, l*64+64): row bits 0..5 (h=1..32)
#pragma unroll
  for (int k = 0; k < 64; k++) {
    int r = l * 64 + k;
    e[k] = col[r ^ l];  // (r>>6)&31 == l
  }
#pragma unroll
  for (int m = 1; m < 64; m <<= 1) {
#pragma unroll
    for (int k = 0; k < 64; k++) {
      if ((k & m) == 0) {
        float a = e[k], bb = e[k | m];
        e[k] = a + bb;
        e[k | m] = a - bb;
      }
    }
  }
#pragma unroll
  for (int k = 0; k < 64; k++) {
    int r = l * 64 + k;
    col[r ^ l] = e[k];
  }
  __syncwarp();

  // phase 2: lane owns rows j*32+l: row bits 6..10 (h=64..1024)
#pragma unroll
  for (int j = 0; j < 64; j++) {
    int r = j * 32 + l;
    e[j] = col[r ^ ((j >> 1) & 31)];
  }
#pragma unroll
  for (int m = 2; m < 64; m <<= 1) {
#pragma unroll
    for (int j = 0; j < 64; j++) {
      if ((j & m) == 0) {
        float a = e[j], bb = e[j | m];
        e[j] = a + bb;
        e[j | m] = a - bb;
      }
    }
  }
#pragma unroll
  for (int j = 0; j < 64; j++) {
    int r = j * 32 + l;
    col[r ^ ((j >> 1) & 31)] = e[j];
  }
  __syncthreads();

  // stage out: thread handles 8 full rows (8 cols = 32B each), *S + truncate
#pragma unroll
  for (int i = 0; i < 8; i++) {
    int r = i * 256 + tid;
    int rs = r ^ ((r >> 6) & 31);
    int kbase = r * 2048 + c0;
    if (kbase < OUTN) {  // OUTN % 8 == 0, row slice never straddles
      float4 s0 = *(const float4*)(S + kbase);
      float4 s1 = *(const float4*)(S + kbase + 4);
      float4 v0, v1;
      v0.x = tile[0 * 2048 + rs] * s0.x;
      v0.y = tile[1 * 2048 + rs] * s0.y;
      v0.z = tile[2 * 2048 + rs] * s0.z;
      v0.w = tile[3 * 2048 + rs] * s0.w;
      v1.x = tile[4 * 2048 + rs] * s1.x;
      v1.y = tile[5 * 2048 + rs] * s1.y;
      v1.z = tile[6 * 2048 + rs] * s1.z;
      v1.w = tile[7 * 2048 + rs] * s1.w;
      float* dst = out + (size_t)b * OUTN + kbase;
      *(float4*)dst = v0;
      *(float4*)(dst + 4) = v1;
    }
  }
}

extern "C" void kernel_launch(void* const* d_in, const int* in_sizes, int n_in,
                              void* d_out, int out_size) {
  const float* x = (const float*)d_in[0];
  const float* B = (const float*)d_in[1];
  const float* G = (const float*)d_in[2];
  const float* S = (const float*)d_in[3];
  const int* Pi = (const int*)d_in[4];
  float* out = (float*)d_out;

  cudaFuncSetAttribute(k_passA, cudaFuncAttributeMaxDynamicSharedMemorySize,
                       65536);
  cudaFuncSetAttribute(k_passB, cudaFuncAttributeMaxDynamicSharedMemorySize,
                       65536);

  k_y<<<1, 256>>>(x, B);
  k_passA<<<2048, 256, 65536>>>(G, Pi);
  k_passB<<<dim3(256, 8), 256, 65536>>>(S, out);
}

// round 4
// speedup vs baseline: 1.0777x; 1.0777x over previous
#include <cuda_runtime.h>
#include <cuda_fp16.h>
#include <cstdint>

#define PADN 4194304
#define OUTN 4000000
#define FULLMASK 0xffffffffu
#define NBLK_A 296

// fp16 scratch: 8 batches x 2^22 halves = 64 MB
static __device__ __half g_work[(size_t)8 * PADN];

// swizzle for 2048-float exchange regions: conflict-free for all our patterns
__device__ __forceinline__ int swz(int r) { return r ^ ((r >> 5) & 31); }

// ---------------------------------------------------------------------------
// Pass A (persistent): computes y = WHT_1024(x*B) once per block, then loops
// over 2048-element chunks: gather y[Pi&1023]*G, 2048-pt WHT, fp16 store.
// 512 threads = 8 pairs (2 warps) x 8 batches; e[32] per thread.
//   phase 1: thread t (0..63) owns idx = j*64+t  -> butterflies bits 6..10
//   exchange (swizzled smem)
//   phase 2: thread t owns idx = t*32+k          -> bit 5 via shfl, bits 0..4
// ---------------------------------------------------------------------------
__global__ void __launch_bounds__(512, 2) k_passA(const float* __restrict__ x,
                                                  const float* __restrict__ B,
                                                  const float* __restrict__ G,
                                                  const int* __restrict__ Pi) {
  extern __shared__ float sm[];
  float* s_y = sm;           // 8192 floats (32 KB)
  float* s_ex = sm + 8192;   // 16384 floats (64 KB)
  const int tid = threadIdx.x;
  const int w = tid >> 5, l = tid & 31;

  // ---- y-table: warps 0..7, warp w = batch w (1024-pt WHT, shfl version)
  if (w < 8) {
    float e[32];
#pragma unroll
    for (int j = 0; j < 32; j++) {
      int i = j * 32 + l;
      e[j] = x[w * 1024 + i] * B[i];
    }
#pragma unroll
    for (int h = 1; h <= 16; h <<= 1) {
      const float sg = (l & h) ? -1.0f : 1.0f;
#pragma unroll
      for (int j = 0; j < 32; j++) {
        float p = __shfl_xor_sync(FULLMASK, e[j], h);
        e[j] = fmaf(sg, e[j], p);
      }
    }
#pragma unroll
    for (int m = 1; m < 32; m <<= 1) {
#pragma unroll
      for (int j = 0; j < 32; j++) {
        if ((j & m) == 0) {
          float a = e[j], b = e[j | m];
          e[j] = a + b;
          e[j | m] = a - b;
        }
      }
    }
#pragma unroll
    for (int j = 0; j < 32; j++) s_y[w * 1024 + j * 32 + l] = e[j];
  }
  __syncthreads();

  const int pair = tid >> 6;   // batch 0..7
  const int t = tid & 63;
  const float* yb = s_y + pair * 1024;
  float* ex = s_ex + pair * 2048;
  const float sg5 = (l & 1) ? -1.0f : 1.0f;

  for (int chunk = blockIdx.x; chunk < 2048; chunk += NBLK_A) {
    const size_t base = (size_t)chunk * 2048;
    float e[32];
    // gather, coalesced (lanes t consecutive)
#pragma unroll
    for (int j = 0; j < 32; j++) {
      size_t gi = base + j * 64 + t;
      e[j] = yb[Pi[gi] & 1023] * G[gi];
    }
    // phase 1: bits 6..10 (j-bits)
#pragma unroll
    for (int m = 1; m < 32; m <<= 1) {
#pragma unroll
      for (int j = 0; j < 32; j++) {
        if ((j & m) == 0) {
          float a = e[j], b = e[j | m];
          e[j] = a + b;
          e[j | m] = a - b;
        }
      }
    }
    __syncthreads();  // previous iteration's exchange reads are done
#pragma unroll
    for (int j = 0; j < 32; j++) ex[swz(j * 64 + t)] = e[j];
    __syncthreads();
#pragma unroll
    for (int k = 0; k < 32; k++) e[k] = ex[swz(t * 32 + k)];
    // bit 5: partner thread t^1 = lane^1
#pragma unroll
    for (int k = 0; k < 32; k++) {
      float p = __shfl_xor_sync(FULLMASK, e[k], 1);
      e[k] = fmaf(sg5, e[k], p);
    }
    // bits 0..4 (k-bits)
#pragma unroll
    for (int m = 1; m < 32; m <<= 1) {
#pragma unroll
      for (int k = 0; k < 32; k++) {
        if ((k & m) == 0) {
          float a = e[k], b = e[k | m];
          e[k] = a + b;
          e[k | m] = a - b;
        }
      }
    }
    // fp16 store: thread owns idx = t*32..t*32+31 -> 64 B contiguous
    __half h[32];
#pragma unroll
    for (int k = 0; k < 32; k++) h[k] = __float2half_rn(e[k]);
    uint4* dst = (uint4*)(g_work + (size_t)pair * PADN + base + t * 32);
    const uint4* hv = (const uint4*)h;
    dst[0] = hv[0];
    dst[1] = hv[1];
    dst[2] = hv[2];
    dst[3] = hv[3];
  }
}

// ---------------------------------------------------------------------------
// Pass B: 2048-pt WHT across chunks (row dim, stride 2048 elements).
// Tile = 2048 rows x 8 cols fp32 (64 KB). 512 threads: column c = tid/64,
// thread t = tid%64 within column, e[32].
//   phase 1: t owns rows r = t*32+k -> bits 0..4 + bit5 (shfl_xor 1)
//   phase 2: t owns rows r = j*64+t -> bits 6..10
// Fused *S and truncation to OUTN on stage-out.
// ---------------------------------------------------------------------------
__global__ void __launch_bounds__(512, 2) k_passB(const float* __restrict__ S,
                                                  float* __restrict__ out) {
  extern __shared__ float tile[];  // 8 * 2048 floats
  const int tid = threadIdx.x;
  const int b = blockIdx.y;
  const int c0 = blockIdx.x * 8;
  const __half* wrk = g_work + (size_t)b * PADN;

  // stage in: thread reads 4 rows, 16 B (8 halfs = full col-slice) each
#pragma unroll
  for (int i = 0; i < 4; i++) {
    int r = i * 512 + tid;
    uint4 v = *(const uint4*)(wrk + (size_t)r * 2048 + c0);
    const __half* hv = (const __half*)&v;
    int rs = swz(r);
#pragma unroll
    for (int c = 0; c < 8; c++) tile[c * 2048 + rs] = __half2float(hv[c]);
  }
  __syncthreads();

  const int col = tid >> 6;
  const int t = tid & 63;
  const int l = tid & 31;
  float* cp = tile + col * 2048;
  const float sg5 = (l & 1) ? -1.0f : 1.0f;
  float e[32];

  // phase 1: rows r = t*32+k -> bits 0..4, then bit 5 via shfl
#pragma unroll
  for (int k = 0; k < 32; k++) e[k] = cp[swz(t * 32 + k)];
#pragma unroll
  for (int m = 1; m < 32; m <<= 1) {
#pragma unroll
    for (int k = 0; k < 32; k++) {
      if ((k & m) == 0) {
        float a = e[k], bb = e[k | m];
        e[k] = a + bb;
        e[k | m] = a - bb;
      }
    }
  }
#pragma unroll
  for (int k = 0; k < 32; k++) {
    float p = __shfl_xor_sync(FULLMASK, e[k], 1);
    e[k] = fmaf(sg5, e[k], p);
  }
#pragma unroll
  for (int k = 0; k < 32; k++) cp[swz(t * 32 + k)] = e[k];
  __syncthreads();

  // phase 2: rows r = j*64+t -> bits 6..10
#pragma unroll
  for (int j = 0; j < 32; j++) e[j] = cp[swz(j * 64 + t)];
#pragma unroll
  for (int m = 1; m < 32; m <<= 1) {
#pragma unroll
    for (int j = 0; j < 32; j++) {
      if ((j & m) == 0) {
        float a = e[j], bb = e[j | m];
        e[j] = a + bb;
        e[j | m] = a - bb;
      }
    }
  }
#pragma unroll
  for (int j = 0; j < 32; j++) cp[swz(j * 64 + t)] = e[j];
  __syncthreads();

  // stage out: thread handles 4 full rows (8 cols = 32 B), *S + truncation
#pragma unroll
  for (int i = 0; i < 4; i++) {
    int r = i * 512 + tid;
    int rs = swz(r);
    int kbase = r * 2048 + c0;
    if (kbase < OUTN) {  // OUTN % 8 == 0 -> slice never straddles the cut
      float4 s0 = *(const float4*)(S + kbase);
      float4 s1 = *(const float4*)(S + kbase + 4);
      float4 v0, v1;
      v0.x = tile[0 * 2048 + rs] * s0.x;
      v0.y = tile[1 * 2048 + rs] * s0.y;
      v0.z = tile[2 * 2048 + rs] * s0.z;
      v0.w = tile[3 * 2048 + rs] * s0.w;
      v1.x = tile[4 * 2048 + rs] * s1.x;
      v1.y = tile[5 * 2048 + rs] * s1.y;
      v1.z = tile[6 * 2048 + rs] * s1.z;
      v1.w = tile[7 * 2048 + rs] * s1.w;
      float* dst = out + (size_t)b * OUTN + kbase;
      *(float4*)dst = v0;
      *(float4*)(dst + 4) = v1;
    }
  }
}

extern "C" void kernel_launch(void* const* d_in, const int* in_sizes, int n_in,
                              void* d_out, int out_size) {
  const float* x = (const float*)d_in[0];
  const float* B = (const float*)d_in[1];
  const float* G = (const float*)d_in[2];
  const float* S = (const float*)d_in[3];
  const int* Pi = (const int*)d_in[4];
  float* out = (float*)d_out;

  cudaFuncSetAttribute(k_passA, cudaFuncAttributeMaxDynamicSharedMemorySize,
                       98304);
  cudaFuncSetAttribute(k_passB, cudaFuncAttributeMaxDynamicSharedMemorySize,
                       65536);

  k_passA<<<NBLK_A, 512, 98304>>>(x, B, G, Pi);
  k_passB<<<dim3(256, 8), 512, 65536>>>(S, out);
}